// round 12
// baseline (speedup 1.0000x reference)
#include <cuda_runtime.h>

// Adaptive avg pool (32,50,50,768) NHWC -> (32,7,7,768), fp32.  FINAL.
// All H/W windows are [7*o, 7*o+8) (size 8, stride 7), avg over 64 elems.
//
// Converged design (R3-R11; CTA-shape sweep 64/256/512/1024 -> 512 optimal):
//  - one thread per output float4: 4704 virtual 64-thread groups packed into
//    588 CTAs x 512 threads <= 148 SMs x 4 CTAs -> exactly one wave, no tail
//  - 32 regs/thread (launch_bounds) -> full 2048-thread SM residency
//  - 64 independent LDG.128 per thread -> ample MLP for DRAM latency
//  - boundary rows (r=7 then r=0) read FIRST: both adjacent-oh sharers touch
//    them nearly simultaneously -> L2 dedup (-29.5 MB DRAM, measured);
//    __ldcg keeps them L2-resident without useless L1 allocation
//  - interior rows r=1..6 (read exactly once chip-wide) via __ldcs streaming;
//    output via __stcs -> no L2 pollution
// Measured: 37.3/37.4/37.9 us bench (replicated), DRAM traffic == 251 MB
// unique floor, ~6.35 TB/s effective HBM BW = practical ceiling (plateau
// across all schedules and cache policies). Remaining idle is the HBM wall;
// all theory-justified levers exhausted and documented.

#define HIN  50
#define WIN  50
#define CV   192   // 768 / 4 float4 lanes per pixel
#define HO   7
#define WO   7

__global__ __launch_bounds__(512, 4)
void adaptive_pool_flat(const float4* __restrict__ in4, float4* __restrict__ out4) {
    // virtual 64-thread group id: 8 per CTA
    const int virt = blockIdx.x * 8 + (threadIdx.x >> 6);  // 0..4703
    const int lane = threadIdx.x & 63;
    const int cseg = virt % 3;
    const int t    = virt / 3;          // 0..1567 = (b*7+oh)*7+ow
    const int ow   = t % WO;
    const int u    = t / WO;            // b*7+oh
    const int oh   = u % HO;
    const int b    = u / HO;
    const int cvec = cseg * 64 + lane;

    const int h0 = oh * 7;
    const int w0 = ow * 7;

    float4 acc = make_float4(0.f, 0.f, 0.f, 0.f);

    const float4* base = in4 + ((size_t)(b * HIN + h0) * WIN + w0) * CV + cvec;

    // Boundary rows first (7 then 0): shared with adjacent-oh windows ->
    // near-simultaneous touch by both sharers -> L2 dedup. __ldcg keeps
    // them L2-resident without L1 allocation.
    #pragma unroll
    for (int c = 0; c < 8; ++c) {
        float4 v = __ldcg(&base[(size_t)(7 * WIN + c) * CV]);
        acc.x += v.x; acc.y += v.y; acc.z += v.z; acc.w += v.w;
    }
    #pragma unroll
    for (int c = 0; c < 8; ++c) {
        float4 v = __ldcg(&base[(size_t)c * CV]);
        acc.x += v.x; acc.y += v.y; acc.z += v.z; acc.w += v.w;
    }

    // Interior rows 1..6: read exactly once chip-wide -> streaming loads.
    #pragma unroll
    for (int r = 1; r < 7; ++r) {
        const float4* row = base + (size_t)r * (WIN * CV);
        #pragma unroll
        for (int c = 0; c < 8; ++c) {
            float4 v = __ldcs(&row[(size_t)c * CV]);
            acc.x += v.x; acc.y += v.y; acc.z += v.z; acc.w += v.w;
        }
    }

    const float s = 1.0f / 64.0f;
    acc.x *= s; acc.y *= s; acc.z *= s; acc.w *= s;
    __stcs(&out4[(size_t)t * CV + cvec], acc);
}

extern "C" void kernel_launch(void* const* d_in, const int* in_sizes, int n_in,
                              void* d_out, int out_size) {
    const float4* in4 = (const float4*)d_in[0];
    float4* out4 = (float4*)d_out;
    adaptive_pool_flat<<<(32 * HO * WO * 3) / 8, 512>>>(in4, out4);
}

// round 14
// speedup vs baseline: 1.0008x; 1.0008x over previous
#include <cuda_runtime.h>

// Adaptive avg pool (32,50,50,768) NHWC -> (32,7,7,768), fp32.  FINAL.
// All H/W windows are [7*o, 7*o+8) (size 8, stride 7), avg over 64 elems.
//
// Converged design (R3-R12; CTA-shape sweep 64/256/512/1024 -> 512 optimal):
//  - one thread per output float4: 4704 virtual 64-thread groups packed into
//    588 CTAs x 512 threads <= 148 SMs x 4 CTAs -> exactly one wave, no tail
//  - 32 regs/thread (launch_bounds) -> full 2048-thread SM residency
//  - 64 independent LDG.128 per thread -> ample MLP for DRAM latency
//  - boundary rows (r=7 then r=0) read FIRST: both adjacent-oh sharers touch
//    them nearly simultaneously -> L2 dedup (-29.5 MB DRAM, measured);
//    __ldcg keeps them L2-resident without useless L1 allocation
//  - interior rows r=1..6 (read exactly once chip-wide) via __ldcs streaming;
//    output via __stcs -> no L2 pollution
// Replicated measurements (identical binary): 37.34/37.38/37.92/39.01 us
// (noise band ~±0.9 us). DRAM traffic == 251 MB unique floor; ~6.1-6.4 TB/s
// effective HBM BW plateau across all schedules and cache policies = the
// practical DRAM wall. All theory-justified levers exhausted; session best
// 37.3 us retained with this source.

#define HIN  50
#define WIN  50
#define CV   192   // 768 / 4 float4 lanes per pixel
#define HO   7
#define WO   7

__global__ __launch_bounds__(512, 4)
void adaptive_pool_flat(const float4* __restrict__ in4, float4* __restrict__ out4) {
    // virtual 64-thread group id: 8 per CTA
    const int virt = blockIdx.x * 8 + (threadIdx.x >> 6);  // 0..4703
    const int lane = threadIdx.x & 63;
    const int cseg = virt % 3;
    const int t    = virt / 3;          // 0..1567 = (b*7+oh)*7+ow
    const int ow   = t % WO;
    const int u    = t / WO;            // b*7+oh
    const int oh   = u % HO;
    const int b    = u / HO;
    const int cvec = cseg * 64 + lane;

    const int h0 = oh * 7;
    const int w0 = ow * 7;

    float4 acc = make_float4(0.f, 0.f, 0.f, 0.f);

    const float4* base = in4 + ((size_t)(b * HIN + h0) * WIN + w0) * CV + cvec;

    // Boundary rows first (7 then 0): shared with adjacent-oh windows ->
    // near-simultaneous touch by both sharers -> L2 dedup. __ldcg keeps
    // them L2-resident without L1 allocation.
    #pragma unroll
    for (int c = 0; c < 8; ++c) {
        float4 v = __ldcg(&base[(size_t)(7 * WIN + c) * CV]);
        acc.x += v.x; acc.y += v.y; acc.z += v.z; acc.w += v.w;
    }
    #pragma unroll
    for (int c = 0; c < 8; ++c) {
        float4 v = __ldcg(&base[(size_t)c * CV]);
        acc.x += v.x; acc.y += v.y; acc.z += v.z; acc.w += v.w;
    }

    // Interior rows 1..6: read exactly once chip-wide -> streaming loads.
    #pragma unroll
    for (int r = 1; r < 7; ++r) {
        const float4* row = base + (size_t)r * (WIN * CV);
        #pragma unroll
        for (int c = 0; c < 8; ++c) {
            float4 v = __ldcs(&row[(size_t)c * CV]);
            acc.x += v.x; acc.y += v.y; acc.z += v.z; acc.w += v.w;
        }
    }

    const float s = 1.0f / 64.0f;
    acc.x *= s; acc.y *= s; acc.z *= s; acc.w *= s;
    __stcs(&out4[(size_t)t * CV + cvec], acc);
}

extern "C" void kernel_launch(void* const* d_in, const int* in_sizes, int n_in,
                              void* d_out, int out_size) {
    const float4* in4 = (const float4*)d_in[0];
    float4* out4 = (float4*)d_out;
    adaptive_pool_flat<<<(32 * HO * WO * 3) / 8, 512>>>(in4, out4);
}

// round 15
// speedup vs baseline: 1.0446x; 1.0437x over previous
#include <cuda_runtime.h>

// Adaptive avg pool (32,50,50,768) NHWC -> (32,7,7,768), fp32.  FINAL.
// All H/W windows are [7*o, 7*o+8) (size 8, stride 7), avg over 64 elems.
//
// Converged design (R3-R14; CTA-shape sweep 64/256/512/1024 -> 512 optimal):
//  - one thread per output float4: 4704 virtual 64-thread groups packed into
//    588 CTAs x 512 threads <= 148 SMs x 4 CTAs -> exactly one wave, no tail
//  - 32 regs/thread (launch_bounds) -> full 2048-thread SM residency
//  - 64 independent LDG.128 per thread -> ample MLP for DRAM latency
//  - boundary rows (r=7 then r=0) read FIRST: both adjacent-oh sharers touch
//    them nearly simultaneously -> L2 dedup (-29.5 MB DRAM, measured);
//    __ldcg keeps them L2-resident without useless L1 allocation
//  - interior rows r=1..6 (read exactly once chip-wide) via __ldcs streaming;
//    output via __stcs -> no L2 pollution
// Replicated (identical binary): 37.34/37.38/37.92/38.98/39.01 us, noise
// ±0.9 us. Traffic == 251 MB unique floor (8x ncu-confirmed). BW plateau
// 6.0-6.4 TB/s across BOTH occupancy/MLP corners (819thr x MLP14 and
// 2048thr x MLP4) -> DRAM-side efficiency ceiling, not request supply.
// All theory-justified levers exhausted; session best 37.3 us is this source.

#define HIN  50
#define WIN  50
#define CV   192   // 768 / 4 float4 lanes per pixel
#define HO   7
#define WO   7

__global__ __launch_bounds__(512, 4)
void adaptive_pool_flat(const float4* __restrict__ in4, float4* __restrict__ out4) {
    // virtual 64-thread group id: 8 per CTA
    const int virt = blockIdx.x * 8 + (threadIdx.x >> 6);  // 0..4703
    const int lane = threadIdx.x & 63;
    const int cseg = virt % 3;
    const int t    = virt / 3;          // 0..1567 = (b*7+oh)*7+ow
    const int ow   = t % WO;
    const int u    = t / WO;            // b*7+oh
    const int oh   = u % HO;
    const int b    = u / HO;
    const int cvec = cseg * 64 + lane;

    const int h0 = oh * 7;
    const int w0 = ow * 7;

    float4 acc = make_float4(0.f, 0.f, 0.f, 0.f);

    const float4* base = in4 + ((size_t)(b * HIN + h0) * WIN + w0) * CV + cvec;

    // Boundary rows first (7 then 0): shared with adjacent-oh windows ->
    // near-simultaneous touch by both sharers -> L2 dedup. __ldcg keeps
    // them L2-resident without L1 allocation.
    #pragma unroll
    for (int c = 0; c < 8; ++c) {
        float4 v = __ldcg(&base[(size_t)(7 * WIN + c) * CV]);
        acc.x += v.x; acc.y += v.y; acc.z += v.z; acc.w += v.w;
    }
    #pragma unroll
    for (int c = 0; c < 8; ++c) {
        float4 v = __ldcg(&base[(size_t)c * CV]);
        acc.x += v.x; acc.y += v.y; acc.z += v.z; acc.w += v.w;
    }

    // Interior rows 1..6: read exactly once chip-wide -> streaming loads.
    #pragma unroll
    for (int r = 1; r < 7; ++r) {
        const float4* row = base + (size_t)r * (WIN * CV);
        #pragma unroll
        for (int c = 0; c < 8; ++c) {
            float4 v = __ldcs(&row[(size_t)c * CV]);
            acc.x += v.x; acc.y += v.y; acc.z += v.z; acc.w += v.w;
        }
    }

    const float s = 1.0f / 64.0f;
    acc.x *= s; acc.y *= s; acc.z *= s; acc.w *= s;
    __stcs(&out4[(size_t)t * CV + cvec], acc);
}

extern "C" void kernel_launch(void* const* d_in, const int* in_sizes, int n_in,
                              void* d_out, int out_size) {
    const float4* in4 = (const float4*)d_in[0];
    float4* out4 = (float4*)d_out;
    adaptive_pool_flat<<<(32 * HO * WO * 3) / 8, 512>>>(in4, out4);
}